// round 11
// baseline (speedup 1.0000x reference)
#include <cuda_runtime.h>
#include <math.h>

#define NPRE   1024
#define NPOST  256
#define MAXB   128

// scan kernel geometry: warp = 8 slices x 4 lanes; each lane owns 2 neurons
#define CH     64                 // k-chunk length
#define NSUB   8                  // slices per chunk
#define KSUB   (CH / NSUB)        // 8 k per slice
#define NTHR   256                // 8 warps
#define NT     64                 // neurons per block (8 per warp x 8 warps)
#define NGRP   (NPOST / NT)       // 4 neuron groups per batch
#define NCHUNK (NPRE / CH)        // 16 chunks
#define CSTRIDE 72                // stride per chunk (8 slices x 9, padded)
#define FULL   0xffffffffu

#define INV_E_F  0.36787944117144233f
#define E_F      2.718281828459045f

// Scratch: packed per-k metadata (s, e^s, s*e^s, idx-bits), one row per batch.
__device__ float4 g_m4[MAXB * NPRE];

// ---------------------------------------------------------------------------
// Kernel 1: stable ascending sort of each batch row (matches jnp.argsort).
// (verified since R4) Emits packed float4 metadata.
// ---------------------------------------------------------------------------
__global__ void __launch_bounds__(512) sort_kernel(const float* __restrict__ spikes)
{
    __shared__ unsigned long long keys[NPRE];
    const int b   = blockIdx.x;
    const int tid = threadIdx.x;

    for (int i = tid; i < NPRE; i += 512) {
        float v = spikes[b * NPRE + i];
        unsigned int bits = __float_as_uint(v);
        bits = (bits & 0x80000000u) ? ~bits : (bits | 0x80000000u);
        keys[i] = ((unsigned long long)bits << 32) | (unsigned int)i;
    }
    __syncthreads();

    for (int k = 2; k <= NPRE; k <<= 1) {
        for (int j = k >> 1; j >= 32; j >>= 1) {
            #pragma unroll
            for (int rep = 0; rep < NPRE / 512; ++rep) {
                int i = tid + rep * 512;
                int ixj = i ^ j;
                if (ixj > i) {
                    unsigned long long A = keys[i];
                    unsigned long long C = keys[ixj];
                    bool up = ((i & k) == 0);
                    if ((A > C) == up) { keys[i] = C; keys[ixj] = A; }
                }
            }
            __syncthreads();
        }
        unsigned long long v0 = keys[tid];
        unsigned long long v1 = keys[tid + 512];
        const bool up0 = ((tid & k) == 0);
        const bool up1 = (((tid + 512) & k) == 0);
        #pragma unroll
        for (int j = 16; j >= 1; j >>= 1) {
            if (j < k) {
                bool lower = ((tid & j) == 0);
                unsigned long long p0 = __shfl_xor_sync(FULL, v0, j);
                unsigned long long p1 = __shfl_xor_sync(FULL, v1, j);
                bool km0 = (lower == up0);
                bool km1 = (lower == up1);
                unsigned long long mn0 = (v0 < p0) ? v0 : p0;
                unsigned long long mx0 = (v0 < p0) ? p0 : v0;
                unsigned long long mn1 = (v1 < p1) ? v1 : p1;
                unsigned long long mx1 = (v1 < p1) ? p1 : v1;
                v0 = km0 ? mn0 : mx0;
                v1 = km1 ? mn1 : mx1;
            }
        }
        keys[tid]       = v0;
        keys[tid + 512] = v1;
        __syncthreads();
    }

    for (int i = tid; i < NPRE; i += 512) {
        unsigned long long kk = keys[i];
        unsigned int hi = (unsigned int)(kk >> 32);
        unsigned int bits = (hi & 0x80000000u) ? (hi ^ 0x80000000u) : ~hi;
        float s = __uint_as_float(bits);
        float e = expf(s);
        g_m4[b * NPRE + i] =
            make_float4(s, e, s * e, __int_as_float((int)(kk & 0xFFFFFFFFu)));
    }
}

// ---------------------------------------------------------------------------
// Lambert W0 on [-1/e, 0): same clip/init/Halley form as the reference.
// ---------------------------------------------------------------------------
__device__ __forceinline__ float lambertw0_dev(float z)
{
    float zc = fminf(fmaxf(z, -INV_E_F + 1e-8f), -1e-30f);
    float w;
    if (zc < -0.2f)
        w = -1.0f + sqrtf(2.0f * fmaf(E_F, zc, 1.0f));
    else
        w = zc * (1.0f - zc);
    #pragma unroll
    for (int it = 0; it < 6; ++it) {
        float ew  = __expf(w);
        float f   = fmaf(w, ew, -zc);
        float wp1 = w + 1.0f;
        float denom = fmaf(2.0f * ew * wp1, wp1, -(w + 2.0f) * f);
        w = w - __fdividef(f * 2.0f * wp1, denom);
    }
    return w;
}

// ---------------------------------------------------------------------------
// Kernel 2: warp-autonomous chunked causal scan, deferred-Lambert resolution.
//   (verified R10) R11 deltas: __launch_bounds__(256,4) -> <=64 regs ->
//   4 blocks/SM -> grid 512 fits one wave; compact stride-9 int index array
//   so the weight prefetch does LDS.32 (conflict-free) instead of LDS.128.
// ---------------------------------------------------------------------------
__global__ void __launch_bounds__(NTHR, 4) scan_kernel(const float* __restrict__ Wmat,
                                                       float* __restrict__ out)
{
    __shared__ float4 sh_m[NCHUNK * CSTRIDE];
    __shared__ int    sh_idx[NCHUNK * CSTRIDE];

    const int b    = blockIdx.x / NGRP;
    const int grp  = blockIdx.x % NGRP;
    const int tid  = threadIdx.x;
    const int wrp  = tid >> 5;
    const int l    = tid & 31;
    const int q    = l >> 2;            // slice 0..7
    const int nl   = l & 3;             // neuron-pair-in-warp 0..3
    const int n0   = grp * NT + wrp * 8 + nl * 2;   // first of 2 neurons
    const int cn   = n0 >> 1;           // float2 column in W
    const int base = b * NPRE;
    const float2* __restrict__ W2 = (const float2*)Wmat;

    // ---- stage metadata once into padded layout ----
    for (int i = tid; i < NPRE; i += NTHR) {
        float4 m = g_m4[base + i];
        int c = i >> 6, qq = (i >> 3) & 7, kk = i & 7;
        int slot = c * CSTRIDE + qq * 9 + kk;
        sh_m[slot]   = m;
        sh_idx[slot] = __float_as_int(m.w);
        if (kk == 0 && i > 0) {          // duplicate into predecessor's slot 8
            int ip = i - 8;
            sh_m[(ip >> 6) * CSTRIDE + ((ip >> 3) & 7) * 9 + 8] = m;
        }
    }
    if (tid == 0)                        // sentinel successor of k=1023
        sh_m[15 * CSTRIDE + 7 * 9 + 8] = make_float4(INFINITY, INFINITY, 0.0f, 0.0f);
    __syncthreads();

    const float4* mp = sh_m   + q * 9;   // this lane's slice, chunk 0
    const int*    ip = sh_idx + q * 9;

    // ---- prologue: chunk-0 weights (2 neurons per lane) ----
    float2 wv[KSUB];
    #pragma unroll
    for (int kk = 0; kk < KSUB; ++kk)
        wv[kk] = __ldg(&W2[ip[kk] * (NPOST >> 1) + cn]);

    bool  done0 = false, done1 = false;
    float arun0 = 0.0f, brun0 = 0.0f, arun1 = 0.0f, brun1 = 0.0f;

    for (int c = 0; c < NCHUNK; ++c) {
        const bool act = !(done0 && done1);

        // ---- slice totals (contiguous conflict-free LDS.128) ----
        float pa0 = 0.0f, pb0 = 0.0f, pa1 = 0.0f, pb1 = 0.0f;
        if (act) {
            #pragma unroll
            for (int kk = 0; kk < KSUB; ++kk) {
                float4 m = mp[kk];
                pa0 = fmaf(wv[kk].x, m.y, pa0);
                pb0 = fmaf(wv[kk].x, m.z, pb0);
                pa1 = fmaf(wv[kk].y, m.y, pa1);
                pb1 = fmaf(wv[kk].y, m.z, pb1);
            }
        }
        // ---- prefetch next chunk weights (index via LDS.32) ----
        float2 wn[KSUB];
        if (act && c + 1 < NCHUNK) {
            #pragma unroll
            for (int kk = 0; kk < KSUB; ++kk)
                wn[kk] = __ldg(&W2[ip[CSTRIDE + kk] * (NPOST >> 1) + cn]);
        }

        // ---- segmented inclusive scan over q (stride-4 lanes) ----
        float ia0 = pa0, ib0 = pb0, ia1 = pa1, ib1 = pb1, t;
        t = __shfl_up_sync(FULL, ia0, 4);  if (q >= 1) ia0 += t;
        t = __shfl_up_sync(FULL, ib0, 4);  if (q >= 1) ib0 += t;
        t = __shfl_up_sync(FULL, ia1, 4);  if (q >= 1) ia1 += t;
        t = __shfl_up_sync(FULL, ib1, 4);  if (q >= 1) ib1 += t;
        t = __shfl_up_sync(FULL, ia0, 8);  if (q >= 2) ia0 += t;
        t = __shfl_up_sync(FULL, ib0, 8);  if (q >= 2) ib0 += t;
        t = __shfl_up_sync(FULL, ia1, 8);  if (q >= 2) ia1 += t;
        t = __shfl_up_sync(FULL, ib1, 8);  if (q >= 2) ib1 += t;
        t = __shfl_up_sync(FULL, ia0, 16); if (q >= 4) ia0 += t;
        t = __shfl_up_sync(FULL, ib0, 16); if (q >= 4) ib0 += t;
        t = __shfl_up_sync(FULL, ia1, 16); if (q >= 4) ia1 += t;
        t = __shfl_up_sync(FULL, ib1, 16); if (q >= 4) ib1 += t;
        float ea0 = ia0 - pa0, eb0 = ib0 - pb0;     // exclusive prefix
        float ea1 = ia1 - pa1, eb1 = ib1 - pb1;
        float tota0 = __shfl_sync(FULL, ia0, 28 + nl);
        float totb0 = __shfl_sync(FULL, ib0, 28 + nl);
        float tota1 = __shfl_sync(FULL, ia1, 28 + nl);
        float totb1 = __shfl_sync(FULL, ib1, 28 + nl);

        // ---- joint concavity prune (sound upper bound; verified R4..R10) ----
        bool flag = false;
        if (act) {
            float a_hi = fmaxf(arun0 + ia0, arun1 + ia1);
            float b_lo = fminf(brun0 + eb0, brun1 + eb1);
            float4 m1 = mp[1];
            float4 m2 = mp[8];
            float la = __logf(a_hi);
            float m;
            if (la <= m1.x)      m = fmaf(a_hi, m1.x, -b_lo) - m1.y;
            else if (la >= m2.x) m = fmaf(a_hi, m2.x, -b_lo) - m2.y;
            else                 m = fmaf(a_hi, la - 1.0f, -b_lo);  // e^la==a_hi
            flag = (m >= -1e-2f);
            if (c == NCHUNK - 1 && q == NSUB - 1) flag = true;  // last-row exemption
        }

        // ---- cheap gate-pass scan (NO Lambert): first pass k + its (a,b) ----
        int   fk0 = 8, fk1 = 8;
        float ca0 = 0.0f, cb0 = 0.0f, ca1 = 0.0f, cb1 = 0.0f;
        if (flag) {
            if (!done0) {
                float aa = arun0 + ea0, bb = brun0 + eb0;
                float4 mc = mp[0];
                #pragma unroll
                for (int kk = 0; kk < KSUB; ++kk) {
                    aa = fmaf(wv[kk].x, mc.y, aa);
                    bb = fmaf(wv[kk].x, mc.z, bb);
                    float4 mn = mp[kk + 1];
                    if (fk0 == 8 && fmaf(aa, mn.x, -bb) >= mn.y) {
                        fk0 = kk; ca0 = aa; cb0 = bb;
                    }
                    mc = mn;
                }
            }
            if (!done1) {
                float aa = arun1 + ea1, bb = brun1 + eb1;
                float4 mc = mp[0];
                #pragma unroll
                for (int kk = 0; kk < KSUB; ++kk) {
                    aa = fmaf(wv[kk].y, mc.y, aa);
                    bb = fmaf(wv[kk].y, mc.z, bb);
                    float4 mn = mp[kk + 1];
                    if (fk1 == 8 && fmaf(aa, mn.x, -bb) >= mn.y) {
                        fk1 = kk; ca1 = aa; cb1 = bb;
                    }
                    mc = mn;
                }
            }
        }

        // ---- min-k resolution: ONE Lambert on the winning lane ----
        unsigned bal0 = __ballot_sync(FULL, fk0 < 8);
        unsigned bal1 = __ballot_sync(FULL, fk1 < 8);
        bool fired0 = false, fired1 = false;
        float t0 = INFINITY, t1 = INFINITY;
        if (bal0 | bal1) {                              // warp-uniform guard
            unsigned gb0 = bal0 & (0x11111111u << nl);
            unsigned gb1 = bal1 & (0x11111111u << nl);
            int src0 = gb0 ? (int)(__ffs(gb0) - 1) : l;
            int src1 = gb1 ? (int)(__ffs(gb1) - 1) : l;
            int ok0 = 0, ok1 = 0;
            if (gb0 && l == src0) {                     // winner eval neuron 0
                float r = __fdividef(cb0, ca0);
                float z = -__fdividef(__expf(r), ca0);
                float tt = r - lambertw0_dev(z);
                ok0 = (ca0 > 0.0f) && (z >= -INV_E_F) && (tt >= mp[fk0].x);
                t0 = tt;
            }
            if (gb1 && l == src1) {                     // winner eval neuron 1
                float r = __fdividef(cb1, ca1);
                float z = -__fdividef(__expf(r), ca1);
                float tt = r - lambertw0_dev(z);
                ok1 = (ca1 > 0.0f) && (z >= -INV_E_F) && (tt >= mp[fk1].x);
                t1 = tt;
            }
            ok0 = __shfl_sync(FULL, ok0, src0);  t0 = __shfl_sync(FULL, t0, src0);
            ok1 = __shfl_sync(FULL, ok1, src1);  t1 = __shfl_sync(FULL, t1, src1);
            fired0 = gb0 && ok0 && !done0;
            fired1 = gb1 && ok1 && !done1;

            // ---- rare fallback: winner invalid -> verified full per-lane scan
            bool nf0 = gb0 && !ok0 && !done0;
            bool nf1 = gb1 && !ok1 && !done1;
            if (__ballot_sync(FULL, nf0 || nf1)) {
                bool  f0 = false, f1 = false;
                float c0 = INFINITY, c1 = INFINITY;
                if (nf0 && flag) {
                    float aa = arun0 + ea0, bb = brun0 + eb0;
                    float4 mc = mp[0];
                    #pragma unroll
                    for (int kk = 0; kk < KSUB; ++kk) {
                        if (!f0) {
                            aa = fmaf(wv[kk].x, mc.y, aa);
                            bb = fmaf(wv[kk].x, mc.z, bb);
                            float4 mn = mp[kk + 1];
                            if (fmaf(aa, mn.x, -bb) >= mn.y) {
                                float r = __fdividef(bb, aa);
                                float z = -__fdividef(__expf(r), aa);
                                bool valid = (aa > 0.0f) && (z >= -INV_E_F);
                                float tt = r - lambertw0_dev(z);
                                if (valid && tt >= mc.x) { f0 = true; c0 = tt; }
                            }
                            mc = mn;
                        }
                    }
                }
                if (nf1 && flag) {
                    float aa = arun1 + ea1, bb = brun1 + eb1;
                    float4 mc = mp[0];
                    #pragma unroll
                    for (int kk = 0; kk < KSUB; ++kk) {
                        if (!f1) {
                            aa = fmaf(wv[kk].y, mc.y, aa);
                            bb = fmaf(wv[kk].y, mc.z, bb);
                            float4 mn = mp[kk + 1];
                            if (fmaf(aa, mn.x, -bb) >= mn.y) {
                                float r = __fdividef(bb, aa);
                                float z = -__fdividef(__expf(r), aa);
                                bool valid = (aa > 0.0f) && (z >= -INV_E_F);
                                float tt = r - lambertw0_dev(z);
                                if (valid && tt >= mc.x) { f1 = true; c1 = tt; }
                            }
                            mc = mn;
                        }
                    }
                }
                unsigned fb0 = __ballot_sync(FULL, f0) & (0x11111111u << nl);
                unsigned fb1 = __ballot_sync(FULL, f1) & (0x11111111u << nl);
                int fs0 = fb0 ? (int)(__ffs(fb0) - 1) : l;
                int fs1 = fb1 ? (int)(__ffs(fb1) - 1) : l;
                float ft0 = __shfl_sync(FULL, c0, fs0);
                float ft1 = __shfl_sync(FULL, c1, fs1);
                if (nf0 && fb0) { fired0 = true; t0 = ft0; }
                if (nf1 && fb1) { fired1 = true; t1 = ft1; }
            }
        }

        // ---- commit chunk results ----
        if (!done0) {
            if (fired0) { done0 = true; if (q == 0) out[b * NPOST + n0] = t0; }
            else        { arun0 += tota0; brun0 += totb0; }
        }
        if (!done1) {
            if (fired1) { done1 = true; if (q == 0) out[b * NPOST + n0 + 1] = t1; }
            else        { arun1 += tota1; brun1 += totb1; }
        }

        if (__all_sync(FULL, done0 && done1)) break;   // warp-local early exit

        #pragma unroll
        for (int kk = 0; kk < KSUB; ++kk) wv[kk] = wn[kk];
        mp += CSTRIDE;
        ip += CSTRIDE;
    }

    if (q == 0) {
        if (!done0) out[b * NPOST + n0]     = INFINITY;
        if (!done1) out[b * NPOST + n0 + 1] = INFINITY;
    }
}

// ---------------------------------------------------------------------------
extern "C" void kernel_launch(void* const* d_in, const int* in_sizes, int n_in,
                              void* d_out, int out_size)
{
    const float* spikes  = (const float*)d_in[0];
    const float* weights = (const float*)d_in[1];
    int sz = in_sizes[0];
    if (n_in >= 2 && in_sizes[0] > in_sizes[1]) {   // robustness to input order
        const float* t = spikes; spikes = weights; weights = t;
        sz = in_sizes[1];
    }
    int B = sz / NPRE;
    sort_kernel<<<B, 512>>>(spikes);
    scan_kernel<<<B * NGRP, NTHR>>>(weights, (float*)d_out);
}

// round 12
// speedup vs baseline: 1.0268x; 1.0268x over previous
#include <cuda_runtime.h>
#include <math.h>

#define NPRE   1024
#define NPOST  256
#define MAXB   128

// scan kernel geometry: warp = 8 slices x 4 lanes; each lane owns 2 neurons
#define CH     64                 // k-chunk length
#define NSUB   8                  // slices per chunk
#define KSUB   (CH / NSUB)        // 8 k per slice
#define NTHR   256                // 8 warps
#define NT     64                 // neurons per block (8 per warp x 8 warps)
#define NGRP   (NPOST / NT)       // 4 neuron groups per batch
#define NCHUNK (NPRE / CH)        // 16 chunks
#define CSTRIDE 72                // stride per chunk (8 slices x 9, padded)
#define FULL   0xffffffffu

#define INV_E_F  0.36787944117144233f
#define E_F      2.718281828459045f

typedef unsigned long long ull;

// Scratch: packed per-k metadata (s, e^s, s*e^s, scaled-row-offset bits).
__device__ float4 g_m4[MAXB * NPRE];

// ---------------------------------------------------------------------------
// Kernel 1: stable ascending sort of each batch row (matches jnp.argsort).
// Key = (order-preserving float bits << 32) | index (stable, verified R4+).
// R12 remap: thread t owns the contiguous pair {2t, 2t+1} -> a warp owns a
// contiguous 64-element span, so stages k=2..64 run ENTIRELY in registers
// (strides 2..32 via shfl_xor, stride 1 in-thread) with no barriers; stages
// k=128..1024 use shared phases only for j>=64 (code identical to verified
// version) + a register phase. 25 -> 15 barriers.
// ---------------------------------------------------------------------------
__global__ void __launch_bounds__(512) sort_kernel(const float* __restrict__ spikes)
{
    __shared__ ull keys[NPRE];
    const int b   = blockIdx.x;
    const int tid = threadIdx.x;

    // load pair into registers, build stable sort keys
    ull e0, e1;
    {
        float v0 = spikes[b * NPRE + 2 * tid];
        float v1 = spikes[b * NPRE + 2 * tid + 1];
        unsigned int b0 = __float_as_uint(v0);
        unsigned int b1 = __float_as_uint(v1);
        b0 = (b0 & 0x80000000u) ? ~b0 : (b0 | 0x80000000u);
        b1 = (b1 & 0x80000000u) ? ~b1 : (b1 | 0x80000000u);
        e0 = ((ull)b0 << 32) | (unsigned int)(2 * tid);
        e1 = ((ull)b1 << 32) | (unsigned int)(2 * tid + 1);
    }

    // ---- stages k = 2..64: all intra-warp, barrier-free ----
    #pragma unroll
    for (int k = 2; k <= 64; k <<= 1) {
        const bool up = (((2 * tid) & k) == 0);      // same for both elements
        #pragma unroll
        for (int j = k >> 1; j >= 2; j >>= 1) {      // strides j via shfl
            int half = j >> 1;                        // lane xor distance
            bool lower = ((tid & half) == 0);         // (i & j)==0 for i=2t
            ull p0 = __shfl_xor_sync(FULL, e0, half);
            ull p1 = __shfl_xor_sync(FULL, e1, half);
            bool keepmin = (lower == up);
            ull mn0 = (e0 < p0) ? e0 : p0, mx0 = (e0 < p0) ? p0 : e0;
            ull mn1 = (e1 < p1) ? e1 : p1, mx1 = (e1 < p1) ? p1 : e1;
            e0 = keepmin ? mn0 : mx0;
            e1 = keepmin ? mn1 : mx1;
        }
        {   // stride j = 1: in-thread (element 2t is the "lower" index)
            ull mn = (e0 < e1) ? e0 : e1, mx = (e0 < e1) ? e1 : e0;
            e0 = up ? mn : mx;
            e1 = up ? mx : mn;
        }
    }
    keys[2 * tid]     = e0;
    keys[2 * tid + 1] = e1;
    __syncthreads();

    // ---- stages k = 128..1024 ----
    for (int k = 128; k <= NPRE; k <<= 1) {
        // shared phases j = k/2 .. 64 (identical to verified code)
        for (int j = k >> 1; j >= 64; j >>= 1) {
            #pragma unroll
            for (int rep = 0; rep < NPRE / 512; ++rep) {
                int i = tid + rep * 512;
                int ixj = i ^ j;
                if (ixj > i) {
                    ull A = keys[i];
                    ull C = keys[ixj];
                    bool up = ((i & k) == 0);
                    if ((A > C) == up) { keys[i] = C; keys[ixj] = A; }
                }
            }
            __syncthreads();
        }
        // register phase j = 32..1 on the contiguous pair
        e0 = keys[2 * tid];
        e1 = keys[2 * tid + 1];
        const bool up = (((2 * tid) & k) == 0);
        #pragma unroll
        for (int j = 32; j >= 2; j >>= 1) {
            int half = j >> 1;
            bool lower = ((tid & half) == 0);
            ull p0 = __shfl_xor_sync(FULL, e0, half);
            ull p1 = __shfl_xor_sync(FULL, e1, half);
            bool keepmin = (lower == up);
            ull mn0 = (e0 < p0) ? e0 : p0, mx0 = (e0 < p0) ? p0 : e0;
            ull mn1 = (e1 < p1) ? e1 : p1, mx1 = (e1 < p1) ? p1 : e1;
            e0 = keepmin ? mn0 : mx0;
            e1 = keepmin ? mn1 : mx1;
        }
        {
            ull mn = (e0 < e1) ? e0 : e1, mx = (e0 < e1) ? e1 : e0;
            e0 = up ? mn : mx;
            e1 = up ? mx : mn;
        }
        keys[2 * tid]     = e0;
        keys[2 * tid + 1] = e1;
        __syncthreads();
    }

    // ---- emit packed metadata; index pre-scaled to float2-row offset ----
    #pragma unroll
    for (int rep = 0; rep < 2; ++rep) {
        int i = 2 * tid + rep;
        ull kk = keys[i];
        unsigned int hi = (unsigned int)(kk >> 32);
        unsigned int bits = (hi & 0x80000000u) ? (hi ^ 0x80000000u) : ~hi;
        float s = __uint_as_float(bits);
        float e = expf(s);
        int row = (int)(kk & 0xFFFFFFFFu);
        g_m4[b * NPRE + i] =
            make_float4(s, e, s * e, __int_as_float(row * (NPOST / 2)));
    }
}

// ---------------------------------------------------------------------------
// Lambert W0 on [-1/e, 0): same clip/init/Halley form as the reference.
// ---------------------------------------------------------------------------
__device__ __forceinline__ float lambertw0_dev(float z)
{
    float zc = fminf(fmaxf(z, -INV_E_F + 1e-8f), -1e-30f);
    float w;
    if (zc < -0.2f)
        w = -1.0f + sqrtf(2.0f * fmaf(E_F, zc, 1.0f));
    else
        w = zc * (1.0f - zc);
    #pragma unroll
    for (int it = 0; it < 6; ++it) {
        float ew  = __expf(w);
        float f   = fmaf(w, ew, -zc);
        float wp1 = w + 1.0f;
        float denom = fmaf(2.0f * ew * wp1, wp1, -(w + 2.0f) * f);
        w = w - __fdividef(f * 2.0f * wp1, denom);
    }
    return w;
}

// ---------------------------------------------------------------------------
// Kernel 2: warp-autonomous chunked causal scan, deferred-Lambert resolution.
// (verified R10/R11; R12 delta: gather uses pre-scaled row offsets)
// ---------------------------------------------------------------------------
__global__ void __launch_bounds__(NTHR, 4) scan_kernel(const float* __restrict__ Wmat,
                                                       float* __restrict__ out)
{
    __shared__ float4 sh_m[NCHUNK * CSTRIDE];
    __shared__ int    sh_idx[NCHUNK * CSTRIDE];

    const int b    = blockIdx.x / NGRP;
    const int grp  = blockIdx.x % NGRP;
    const int tid  = threadIdx.x;
    const int wrp  = tid >> 5;
    const int l    = tid & 31;
    const int q    = l >> 2;            // slice 0..7
    const int nl   = l & 3;             // neuron-pair-in-warp 0..3
    const int n0   = grp * NT + wrp * 8 + nl * 2;   // first of 2 neurons
    const int cn   = n0 >> 1;           // float2 column in W
    const int base = b * NPRE;
    const float2* __restrict__ W2 = (const float2*)Wmat;

    // ---- stage metadata once into padded layout ----
    for (int i = tid; i < NPRE; i += NTHR) {
        float4 m = g_m4[base + i];
        int c = i >> 6, qq = (i >> 3) & 7, kk = i & 7;
        int slot = c * CSTRIDE + qq * 9 + kk;
        sh_m[slot]   = m;
        sh_idx[slot] = __float_as_int(m.w);          // pre-scaled row offset
        if (kk == 0 && i > 0) {          // duplicate into predecessor's slot 8
            int ipx = i - 8;
            sh_m[(ipx >> 6) * CSTRIDE + ((ipx >> 3) & 7) * 9 + 8] = m;
        }
    }
    if (tid == 0)                        // sentinel successor of k=1023
        sh_m[15 * CSTRIDE + 7 * 9 + 8] = make_float4(INFINITY, INFINITY, 0.0f, 0.0f);
    __syncthreads();

    const float4* mp = sh_m   + q * 9;   // this lane's slice, chunk 0
    const int*    ip = sh_idx + q * 9;

    // ---- prologue: chunk-0 weights (2 neurons per lane) ----
    float2 wv[KSUB];
    #pragma unroll
    for (int kk = 0; kk < KSUB; ++kk)
        wv[kk] = __ldg(&W2[ip[kk] + cn]);

    bool  done0 = false, done1 = false;
    float arun0 = 0.0f, brun0 = 0.0f, arun1 = 0.0f, brun1 = 0.0f;

    for (int c = 0; c < NCHUNK; ++c) {
        const bool act = !(done0 && done1);

        // ---- slice totals (contiguous conflict-free LDS.128) ----
        float pa0 = 0.0f, pb0 = 0.0f, pa1 = 0.0f, pb1 = 0.0f;
        if (act) {
            #pragma unroll
            for (int kk = 0; kk < KSUB; ++kk) {
                float4 m = mp[kk];
                pa0 = fmaf(wv[kk].x, m.y, pa0);
                pb0 = fmaf(wv[kk].x, m.z, pb0);
                pa1 = fmaf(wv[kk].y, m.y, pa1);
                pb1 = fmaf(wv[kk].y, m.z, pb1);
            }
        }
        // ---- prefetch next chunk weights (index via LDS.32, no IMAD) ----
        float2 wn[KSUB];
        if (act && c + 1 < NCHUNK) {
            #pragma unroll
            for (int kk = 0; kk < KSUB; ++kk)
                wn[kk] = __ldg(&W2[ip[CSTRIDE + kk] + cn]);
        }

        // ---- segmented inclusive scan over q (stride-4 lanes) ----
        float ia0 = pa0, ib0 = pb0, ia1 = pa1, ib1 = pb1, t;
        t = __shfl_up_sync(FULL, ia0, 4);  if (q >= 1) ia0 += t;
        t = __shfl_up_sync(FULL, ib0, 4);  if (q >= 1) ib0 += t;
        t = __shfl_up_sync(FULL, ia1, 4);  if (q >= 1) ia1 += t;
        t = __shfl_up_sync(FULL, ib1, 4);  if (q >= 1) ib1 += t;
        t = __shfl_up_sync(FULL, ia0, 8);  if (q >= 2) ia0 += t;
        t = __shfl_up_sync(FULL, ib0, 8);  if (q >= 2) ib0 += t;
        t = __shfl_up_sync(FULL, ia1, 8);  if (q >= 2) ia1 += t;
        t = __shfl_up_sync(FULL, ib1, 8);  if (q >= 2) ib1 += t;
        t = __shfl_up_sync(FULL, ia0, 16); if (q >= 4) ia0 += t;
        t = __shfl_up_sync(FULL, ib0, 16); if (q >= 4) ib0 += t;
        t = __shfl_up_sync(FULL, ia1, 16); if (q >= 4) ia1 += t;
        t = __shfl_up_sync(FULL, ib1, 16); if (q >= 4) ib1 += t;
        float ea0 = ia0 - pa0, eb0 = ib0 - pb0;     // exclusive prefix
        float ea1 = ia1 - pa1, eb1 = ib1 - pb1;
        float tota0 = __shfl_sync(FULL, ia0, 28 + nl);
        float totb0 = __shfl_sync(FULL, ib0, 28 + nl);
        float tota1 = __shfl_sync(FULL, ia1, 28 + nl);
        float totb1 = __shfl_sync(FULL, ib1, 28 + nl);

        // ---- joint concavity prune (sound upper bound; verified R4..R11) ----
        bool flag = false;
        if (act) {
            float a_hi = fmaxf(arun0 + ia0, arun1 + ia1);
            float b_lo = fminf(brun0 + eb0, brun1 + eb1);
            float4 m1 = mp[1];
            float4 m2 = mp[8];
            float la = __logf(a_hi);
            float m;
            if (la <= m1.x)      m = fmaf(a_hi, m1.x, -b_lo) - m1.y;
            else if (la >= m2.x) m = fmaf(a_hi, m2.x, -b_lo) - m2.y;
            else                 m = fmaf(a_hi, la - 1.0f, -b_lo);  // e^la==a_hi
            flag = (m >= -1e-2f);
            if (c == NCHUNK - 1 && q == NSUB - 1) flag = true;  // last-row exemption
        }

        // ---- cheap gate-pass scan (NO Lambert): first pass k + its (a,b) ----
        int   fk0 = 8, fk1 = 8;
        float ca0 = 0.0f, cb0 = 0.0f, ca1 = 0.0f, cb1 = 0.0f;
        if (flag) {
            if (!done0) {
                float aa = arun0 + ea0, bb = brun0 + eb0;
                float4 mc = mp[0];
                #pragma unroll
                for (int kk = 0; kk < KSUB; ++kk) {
                    aa = fmaf(wv[kk].x, mc.y, aa);
                    bb = fmaf(wv[kk].x, mc.z, bb);
                    float4 mn = mp[kk + 1];
                    if (fk0 == 8 && fmaf(aa, mn.x, -bb) >= mn.y) {
                        fk0 = kk; ca0 = aa; cb0 = bb;
                    }
                    mc = mn;
                }
            }
            if (!done1) {
                float aa = arun1 + ea1, bb = brun1 + eb1;
                float4 mc = mp[0];
                #pragma unroll
                for (int kk = 0; kk < KSUB; ++kk) {
                    aa = fmaf(wv[kk].y, mc.y, aa);
                    bb = fmaf(wv[kk].y, mc.z, bb);
                    float4 mn = mp[kk + 1];
                    if (fk1 == 8 && fmaf(aa, mn.x, -bb) >= mn.y) {
                        fk1 = kk; ca1 = aa; cb1 = bb;
                    }
                    mc = mn;
                }
            }
        }

        // ---- min-k resolution: ONE Lambert on the winning lane ----
        unsigned bal0 = __ballot_sync(FULL, fk0 < 8);
        unsigned bal1 = __ballot_sync(FULL, fk1 < 8);
        bool fired0 = false, fired1 = false;
        float t0 = INFINITY, t1 = INFINITY;
        if (bal0 | bal1) {                              // warp-uniform guard
            unsigned gb0 = bal0 & (0x11111111u << nl);
            unsigned gb1 = bal1 & (0x11111111u << nl);
            int src0 = gb0 ? (int)(__ffs(gb0) - 1) : l;
            int src1 = gb1 ? (int)(__ffs(gb1) - 1) : l;
            int ok0 = 0, ok1 = 0;
            if (gb0 && l == src0) {                     // winner eval neuron 0
                float r = __fdividef(cb0, ca0);
                float z = -__fdividef(__expf(r), ca0);
                float tt = r - lambertw0_dev(z);
                ok0 = (ca0 > 0.0f) && (z >= -INV_E_F) && (tt >= mp[fk0].x);
                t0 = tt;
            }
            if (gb1 && l == src1) {                     // winner eval neuron 1
                float r = __fdividef(cb1, ca1);
                float z = -__fdividef(__expf(r), ca1);
                float tt = r - lambertw0_dev(z);
                ok1 = (ca1 > 0.0f) && (z >= -INV_E_F) && (tt >= mp[fk1].x);
                t1 = tt;
            }
            ok0 = __shfl_sync(FULL, ok0, src0);  t0 = __shfl_sync(FULL, t0, src0);
            ok1 = __shfl_sync(FULL, ok1, src1);  t1 = __shfl_sync(FULL, t1, src1);
            fired0 = gb0 && ok0 && !done0;
            fired1 = gb1 && ok1 && !done1;

            // ---- rare fallback: winner invalid -> verified full per-lane scan
            bool nf0 = gb0 && !ok0 && !done0;
            bool nf1 = gb1 && !ok1 && !done1;
            if (__ballot_sync(FULL, nf0 || nf1)) {
                bool  f0 = false, f1 = false;
                float c0 = INFINITY, c1 = INFINITY;
                if (nf0 && flag) {
                    float aa = arun0 + ea0, bb = brun0 + eb0;
                    float4 mc = mp[0];
                    #pragma unroll
                    for (int kk = 0; kk < KSUB; ++kk) {
                        if (!f0) {
                            aa = fmaf(wv[kk].x, mc.y, aa);
                            bb = fmaf(wv[kk].x, mc.z, bb);
                            float4 mn = mp[kk + 1];
                            if (fmaf(aa, mn.x, -bb) >= mn.y) {
                                float r = __fdividef(bb, aa);
                                float z = -__fdividef(__expf(r), aa);
                                bool valid = (aa > 0.0f) && (z >= -INV_E_F);
                                float tt = r - lambertw0_dev(z);
                                if (valid && tt >= mc.x) { f0 = true; c0 = tt; }
                            }
                            mc = mn;
                        }
                    }
                }
                if (nf1 && flag) {
                    float aa = arun1 + ea1, bb = brun1 + eb1;
                    float4 mc = mp[0];
                    #pragma unroll
                    for (int kk = 0; kk < KSUB; ++kk) {
                        if (!f1) {
                            aa = fmaf(wv[kk].y, mc.y, aa);
                            bb = fmaf(wv[kk].y, mc.z, bb);
                            float4 mn = mp[kk + 1];
                            if (fmaf(aa, mn.x, -bb) >= mn.y) {
                                float r = __fdividef(bb, aa);
                                float z = -__fdividef(__expf(r), aa);
                                bool valid = (aa > 0.0f) && (z >= -INV_E_F);
                                float tt = r - lambertw0_dev(z);
                                if (valid && tt >= mc.x) { f1 = true; c1 = tt; }
                            }
                            mc = mn;
                        }
                    }
                }
                unsigned fb0 = __ballot_sync(FULL, f0) & (0x11111111u << nl);
                unsigned fb1 = __ballot_sync(FULL, f1) & (0x11111111u << nl);
                int fs0 = fb0 ? (int)(__ffs(fb0) - 1) : l;
                int fs1 = fb1 ? (int)(__ffs(fb1) - 1) : l;
                float ft0 = __shfl_sync(FULL, c0, fs0);
                float ft1 = __shfl_sync(FULL, c1, fs1);
                if (nf0 && fb0) { fired0 = true; t0 = ft0; }
                if (nf1 && fb1) { fired1 = true; t1 = ft1; }
            }
        }

        // ---- commit chunk results ----
        if (!done0) {
            if (fired0) { done0 = true; if (q == 0) out[b * NPOST + n0] = t0; }
            else        { arun0 += tota0; brun0 += totb0; }
        }
        if (!done1) {
            if (fired1) { done1 = true; if (q == 0) out[b * NPOST + n0 + 1] = t1; }
            else        { arun1 += tota1; brun1 += totb1; }
        }

        if (__all_sync(FULL, done0 && done1)) break;   // warp-local early exit

        #pragma unroll
        for (int kk = 0; kk < KSUB; ++kk) wv[kk] = wn[kk];
        mp += CSTRIDE;
        ip += CSTRIDE;
    }

    if (q == 0) {
        if (!done0) out[b * NPOST + n0]     = INFINITY;
        if (!done1) out[b * NPOST + n0 + 1] = INFINITY;
    }
}

// ---------------------------------------------------------------------------
extern "C" void kernel_launch(void* const* d_in, const int* in_sizes, int n_in,
                              void* d_out, int out_size)
{
    const float* spikes  = (const float*)d_in[0];
    const float* weights = (const float*)d_in[1];
    int sz = in_sizes[0];
    if (n_in >= 2 && in_sizes[0] > in_sizes[1]) {   // robustness to input order
        const float* t = spikes; spikes = weights; weights = t;
        sz = in_sizes[1];
    }
    int B = sz / NPRE;
    sort_kernel<<<B, 512>>>(spikes);
    scan_kernel<<<B * NGRP, NTHR>>>(weights, (float*)d_out);
}